// round 6
// baseline (speedup 1.0000x reference)
#include <cuda_runtime.h>
#include <cuda_bf16.h>
#include <cstdint>

// Hamming1Layer fused kernel, v4 (SIMT; tcgen05 unavailable: harness PTX targets sm_103).
// y[b,c,l] = (w_self*x[b,c,l] + sum_k w_bits[k]*x[b,c,l^(1<<k)]) / 15
// out[b,o,l] = sum_c mix_w[o,c]*y[b,c,l] + mix_b[o]
// B=32, C_IN=32, C_OUT=64, L=16384, N_BITS=14.
//
// v4 vs v2 (113us, L1=72.5%):
//  - quad (float4) gather: bits 0,1 are register permutes (not loads)
//  - bf16 SMEM x-tile for neighbor bits 2..8 (halves in-tile LDS bytes;
//    self + bits 0,1 stay f32 -> rel_err ~4e-4)
//  - TILE_L=512: only bits 9..13 from global (L2-hot)
//  - mix: 8o x 4p tile, LDS.128 w/y with lane layout (og,pg)=(8,4) ->
//    broadcast-merged wavefronts: 6 wf per c per warp (was 16)

#define NBITS   14
#define LPOW    16384
#define CIN     32
#define COUT    64
#define TILE_L  512
#define QUADS   (TILE_L / 4)      // 128
#define TPB     256

// ---- smem map (bytes) ----
#define SMEM_XB    0                            // bf16 [CIN][TILE_L] = 32 KiB
#define SMEM_Y     (CIN * TILE_L * 2)           // f32  [CIN][TILE_L] = 64 KiB
#define SMEM_WF    (SMEM_Y + CIN * TILE_L * 4)  // f32  [CIN][COUT]   =  8 KiB
#define SMEM_B     (SMEM_WF + CIN * COUT * 4)   // u64  [COUT]        = 512 B
#define SMEM_TOTAL (SMEM_B + COUT * 8)          // ~105 KiB -> 2 blocks/SM

__device__ __forceinline__ uint64_t pack2(float lo, float hi) {
    uint64_t r;
    asm("mov.b64 %0, {%1, %2};" : "=l"(r) : "f"(lo), "f"(hi));
    return r;
}
__device__ __forceinline__ void unpack2(uint64_t v, float& lo, float& hi) {
    asm("mov.b64 {%0, %1}, %2;" : "=f"(lo), "=f"(hi) : "l"(v));
}
__device__ __forceinline__ uint64_t fma2(uint64_t a, uint64_t b, uint64_t c) {
    uint64_t d;
    asm("fma.rn.f32x2 %0, %1, %2, %3;" : "=l"(d) : "l"(a), "l"(b), "l"(c));
    return d;
}
__device__ __forceinline__ uint64_t mul2(uint64_t a, uint64_t b) {
    uint64_t d;
    asm("mul.rn.f32x2 %0, %1, %2;" : "=l"(d) : "l"(a), "l"(b));
    return d;
}
// bf16x2 word (hi=elem1, lo=elem0) -> f32x2 pair (lo=elem0, hi=elem1)
__device__ __forceinline__ uint64_t bfp_to_f32x2(uint32_t v) {
    uint32_t lo = v << 16;
    uint32_t hi = v & 0xFFFF0000u;
    uint64_t r;
    asm("mov.b64 %0, {%1, %2};" : "=l"(r) : "r"(lo), "r"(hi));
    return r;
}
// two f32 -> bf16x2 word (a -> lo, b -> hi)
__device__ __forceinline__ uint32_t f2_to_bfp(float a, float b) {
    uint32_t r;
    asm("cvt.rn.bf16x2.f32 %0, %1, %2;" : "=r"(r) : "f"(b), "f"(a));
    return r;
}

extern __shared__ unsigned char smem_raw[];

__global__ __launch_bounds__(TPB, 2)
void hamming_kernel(const float* __restrict__ x,
                    const float* __restrict__ w_self,
                    const float* __restrict__ w_bits,
                    const float* __restrict__ mix_w,
                    const float* __restrict__ mix_b,
                    float* __restrict__ out)
{
    uint32_t*  sh_xb = (uint32_t*)(smem_raw + SMEM_XB);   // bf16x2 words [c][TILE_L/2]
    float*     sh_y  = (float*)  (smem_raw + SMEM_Y);     // [c][TILE_L]
    float*     sh_wf = (float*)  (smem_raw + SMEM_WF);    // [c][COUT], 1/15 folded
    uint64_t*  sh_b  = (uint64_t*)(smem_raw + SMEM_B);    // packed (b,b)

    const int tid   = threadIdx.x;
    const int tile  = blockIdx.x;            // 0..31
    const int b     = blockIdx.y;            // 0..31
    const int lbase = tile * TILE_L;

    // ---- stage mix weights (1/15 folded) + bias ----
    const float inv15 = 1.0f / 15.0f;
    for (int e = tid; e < CIN * COUT; e += TPB) {
        int o = e & 63, c = e >> 6;                 // write coalesced over o
        sh_wf[c * COUT + o] = mix_w[o * CIN + c] * inv15;   // mix_w L2-hot across blocks
    }
    if (tid < COUT) {
        float v = mix_b[tid];
        sh_b[tid] = pack2(v, v);
    }

    // ---- stage bf16 x tile: x[b, :, lbase:lbase+512] ----
    const float4* xg4 = (const float4*)(x + (size_t)b * CIN * LPOW);
    #pragma unroll
    for (int i = 0; i < (CIN * TILE_L / 4) / TPB; ++i) {    // 16 iters
        int j  = i * TPB + tid;          // float4 slot
        int c  = j >> 7;                 // TILE_L/4 = 128 per c
        int lw = j & 127;
        float4 f = xg4[(size_t)c * (LPOW / 4) + (lbase >> 2) + lw];
        uint2 p;
        p.x = f2_to_bfp(f.x, f.y);
        p.y = f2_to_bfp(f.z, f.w);
        *(uint2*)(sh_xb + c * (TILE_L / 2) + lw * 2) = p;
    }

    // per-thread packed weights
    const float ws = *w_self;
    const uint64_t ws2 = pack2(ws, ws);
    uint64_t wb2[NBITS];
    #pragma unroll
    for (int k = 0; k < NBITS; ++k) {
        float v = w_bits[k];
        wb2[k] = pack2(v, v);
    }
    __syncthreads();

    // ================= gather: item = (c, quad of 4 l) =================
    // lanes cover consecutive quads of the same c -> coalesced everywhere.
    const float* xb = x + (size_t)b * CIN * LPOW;
    #pragma unroll 2
    for (int it = 0; it < (CIN * QUADS) / TPB; ++it) {      // 16 iters
        int idx = it * TPB + tid;
        int c   = idx >> 7;              // QUADS=128 per c
        int q   = idx & 127;

        const float4*   xc4 = (const float4*)(xb + (size_t)c * LPOW);
        const uint32_t* row = sh_xb + c * (TILE_L / 2);

        // self quad (f32, L1-hot: staged moments ago)
        float4 s = xc4[(lbase >> 2) + q];

        // self + bit0 (in-pair swap) + bit1 (pair swap) from registers
        uint64_t s01 = pack2(s.x, s.y), s23 = pack2(s.z, s.w);
        uint64_t a01 = mul2(ws2, s01);
        uint64_t a23 = mul2(ws2, s23);
        a01 = fma2(wb2[0], pack2(s.y, s.x), a01);
        a23 = fma2(wb2[0], pack2(s.w, s.z), a23);
        a01 = fma2(wb2[1], s23, a01);
        a23 = fma2(wb2[1], s01, a23);

        // bits 2..8: bf16 quads from SMEM tile
        #pragma unroll
        for (int k = 2; k <= 8; ++k) {
            int qn = q ^ (1 << (k - 2));            // neighbor quad index
            uint2 n = *(const uint2*)(row + qn * 2);
            a01 = fma2(wb2[k], bfp_to_f32x2(n.x), a01);
            a23 = fma2(wb2[k], bfp_to_f32x2(n.y), a23);
        }

        // bits 9..13: f32 quads from global (L2-hot)
        #pragma unroll
        for (int k = 9; k < NBITS; ++k) {
            float4 g = xc4[((lbase ^ (1 << k)) >> 2) + q];
            a01 = fma2(wb2[k], pack2(g.x, g.y), a01);
            a23 = fma2(wb2[k], pack2(g.z, g.w), a23);
        }

        // store y quad (f32)
        float y0, y1, y2, y3;
        unpack2(a01, y0, y1);
        unpack2(a23, y2, y3);
        *(float4*)(sh_y + c * TILE_L + q * 4) = make_float4(y0, y1, y2, y3);
    }
    __syncthreads();

    // ================= mix: 8o x 4p register tile, 2 pair-halves ===========
    // lane = (og, pg): og = (tid%32)/4 in [0,8), pg = tid%4.
    // warp wv owns pairs [half*128 + wv*16, +16); thread: pg*4 + {0..3}.
    const int og = (tid & 31) >> 2;
    const int pg = tid & 3;
    const int wv = tid >> 5;
    const int ob = og * 8;

    uint64_t* outp = (uint64_t*)out + (size_t)b * COUT * (LPOW / 2) + (lbase >> 1);

    #pragma unroll
    for (int ph = 0; ph < 2; ++ph) {
        const int pbase = ph * 128 + wv * 16 + pg * 4;   // first pair of this thread
        const int ebase = 2 * pbase;                     // f32 element offset

        uint64_t acc[8][4];
        #pragma unroll
        for (int i = 0; i < 8; ++i) {
            uint64_t bias = sh_b[ob + i];
            #pragma unroll
            for (int j = 0; j < 4; ++j) acc[i][j] = bias;
        }

        #pragma unroll 4
        for (int c = 0; c < CIN; ++c) {
            // w: 8 f32 (o = ob..ob+8), broadcast across pg lanes -> 2 wf
            const float4* wr = (const float4*)(sh_wf + c * COUT + ob);
            float4 wA = wr[0], wB = wr[1];
            uint64_t w8[8];
            w8[0] = pack2(wA.x, wA.x); w8[1] = pack2(wA.y, wA.y);
            w8[2] = pack2(wA.z, wA.z); w8[3] = pack2(wA.w, wA.w);
            w8[4] = pack2(wB.x, wB.x); w8[5] = pack2(wB.y, wB.y);
            w8[6] = pack2(wB.z, wB.z); w8[7] = pack2(wB.w, wB.w);

            // y: 8 f32 = 4 pairs, broadcast across og lanes -> 1-2 wf
            const float4* yr = (const float4*)(sh_y + c * TILE_L + ebase);
            float4 yA = yr[0], yB = yr[1];
            uint64_t y4[4];
            y4[0] = pack2(yA.x, yA.y); y4[1] = pack2(yA.z, yA.w);
            y4[2] = pack2(yB.x, yB.y); y4[3] = pack2(yB.z, yB.w);

            #pragma unroll
            for (int i = 0; i < 8; ++i)
                #pragma unroll
                for (int j = 0; j < 4; ++j)
                    acc[i][j] = fma2(w8[i], y4[j], acc[i][j]);
        }

        #pragma unroll
        for (int i = 0; i < 8; ++i) {
            uint64_t* orow = outp + (size_t)(ob + i) * (LPOW / 2) + pbase;
            #pragma unroll
            for (int j = 0; j < 4; ++j)
                orow[j] = acc[i][j];
        }
    }
}

extern "C" void kernel_launch(void* const* d_in, const int* in_sizes, int n_in,
                              void* d_out, int out_size)
{
    const float* x      = (const float*)d_in[0];
    const float* w_self = (const float*)d_in[1];
    const float* w_bits = (const float*)d_in[2];
    const float* mix_w  = (const float*)d_in[3];
    const float* mix_b  = (const float*)d_in[4];
    float* out = (float*)d_out;

    cudaFuncSetAttribute(hamming_kernel,
                         cudaFuncAttributeMaxDynamicSharedMemorySize, SMEM_TOTAL);

    dim3 grid(LPOW / TILE_L, 32, 1);   // (32 tiles, 32 batches) = 1024 blocks
    hamming_kernel<<<grid, TPB, SMEM_TOTAL>>>(x, w_self, w_bits, mix_w, mix_b, out);
}